// round 2
// baseline (speedup 1.0000x reference)
#include <cuda_runtime.h>
#include <cuda_bf16.h>

// Problem constants (fixed by the reference):
//   B=4096 scenes, L=200 padded tokens, V=50000 vocab, H=128 hidden.
// out[i,h] = b[h] + sum_{j < len_i} W[h, tokens[i,j]]
// Strategy: transpose W -> Wt[V,H] (contiguous 512B rows), then one warp per
// scene gathers+sums rows of Wt. W fits in L2 (25.6MB), so the gather is
// L2-bandwidth bound.

#define B_N 4096
#define L_N 200
#define V_N 50000
#define H_N 128

// Scratch: transposed weights, [V, H] row-major. 25.6 MB static device array
// (allocation-free per harness rules).
__device__ float g_Wt[(size_t)V_N * H_N];

// ---------------------------------------------------------------------------
// Tiled transpose: W[H,V] row-major -> g_Wt[V,H] row-major.
// Block (32,8), grid (ceil(V/32), H/32). Shared tile with +1 padding.
// ---------------------------------------------------------------------------
__global__ void __launch_bounds__(256) transpose_W_kernel(const float* __restrict__ W) {
    __shared__ float tile[32][33];
    int v0 = blockIdx.x * 32;
    int h0 = blockIdx.y * 32;
    int x = threadIdx.x;          // 0..31
    int y = threadIdx.y;          // 0..7

    // Read: rows of W (coalesced along v)
    #pragma unroll
    for (int i = 0; i < 32; i += 8) {
        int v = v0 + x;
        int h = h0 + y + i;
        if (v < V_N) tile[y + i][x] = W[(size_t)h * V_N + v];
    }
    __syncthreads();
    // Write: rows of Wt (coalesced along h)
    #pragma unroll
    for (int i = 0; i < 32; i += 8) {
        int v = v0 + y + i;
        int h = h0 + x;
        if (v < V_N) g_Wt[(size_t)v * H_N + h] = tile[x][y + i];
    }
}

// ---------------------------------------------------------------------------
// Gather-sum: one warp per scene. Lane owns 4 consecutive h via float4.
// Tokens loaded coalesced in chunks of 32, broadcast with shfl.
// ---------------------------------------------------------------------------
__global__ void __launch_bounds__(256) bow_gather_kernel(
    const int* __restrict__ tokens,
    const int* __restrict__ lengths,
    const float* __restrict__ bias,
    float* __restrict__ out)
{
    int gwarp = (int)((blockIdx.x * blockDim.x + threadIdx.x) >> 5);
    int lane  = threadIdx.x & 31;
    if (gwarp >= B_N) return;

    int len = lengths[gwarp];
    const int* tok = tokens + (size_t)gwarp * L_N;

    // acc starts at bias (lane -> h = 4*lane .. 4*lane+3)
    float4 acc = reinterpret_cast<const float4*>(bias)[lane];

    int nfull = len & ~31;
    for (int j0 = 0; j0 < nfull; j0 += 32) {
        int myTok = tok[j0 + lane];            // coalesced token chunk
        #pragma unroll 8
        for (int k = 0; k < 32; k++) {
            int t = __shfl_sync(0xffffffffu, myTok, k);
            float4 w = reinterpret_cast<const float4*>(g_Wt + (size_t)t * H_N)[lane];
            acc.x += w.x; acc.y += w.y; acc.z += w.z; acc.w += w.w;
        }
    }
    int rem = len - nfull;
    if (rem > 0) {
        int jj = nfull + lane;
        int myTok = tok[jj < L_N ? jj : (L_N - 1)];   // stay in-bounds; unused lanes ignored
        for (int k = 0; k < rem; k++) {
            int t = __shfl_sync(0xffffffffu, myTok, k);
            float4 w = reinterpret_cast<const float4*>(g_Wt + (size_t)t * H_N)[lane];
            acc.x += w.x; acc.y += w.y; acc.z += w.z; acc.w += w.w;
        }
    }

    reinterpret_cast<float4*>(out + (size_t)gwarp * H_N)[lane] = acc;
}

// ---------------------------------------------------------------------------
// kernel_launch: transpose then gather, same (default) stream, graph-capturable.
// Inputs (metadata order): tokens[int32, B*L], lengths[int32, B],
//                          W[f32, H*V], b[f32, H]. Output: f32 [B, H].
// ---------------------------------------------------------------------------
extern "C" void kernel_launch(void* const* d_in, const int* in_sizes, int n_in,
                              void* d_out, int out_size) {
    const int*   tokens  = (const int*)d_in[0];
    const int*   lengths = (const int*)d_in[1];
    const float* W       = (const float*)d_in[2];
    const float* bias    = (const float*)d_in[3];
    float*       out     = (float*)d_out;

    (void)in_sizes; (void)n_in; (void)out_size;

    dim3 tgrid((V_N + 31) / 32, H_N / 32);
    dim3 tblock(32, 8);
    transpose_W_kernel<<<tgrid, tblock>>>(W);

    // 4096 warps, 8 warps (256 threads) per block -> 512 blocks
    int threads = 256;
    int warpsPerBlock = threads / 32;
    int blocks = (B_N + warpsPerBlock - 1) / warpsPerBlock;
    bow_gather_kernel<<<blocks, threads>>>(tokens, lengths, bias, out);
}

// round 3
// speedup vs baseline: 1.1503x; 1.1503x over previous
#include <cuda_runtime.h>
#include <cuda_bf16.h>

// B=4096 scenes, L=200 padded tokens, V=50000 vocab, H=128 hidden.
// out[i,h] = b[h] + sum_{j < len_i} W[h, tokens[i,j]]
// Wt[V,H] transpose (contiguous 512B rows, fits L2), then gather-sum.
// R2: 4 warps per scene (1 block/scene) to fix latency/occupancy bound seen
// in ncu (occ 27%, issue 16%, L2 33% -- nothing saturated).

#define B_N 4096
#define L_N 200
#define V_N 50000
#define H_N 128

__device__ float g_Wt[(size_t)V_N * H_N];   // 25.6 MB scratch (allocation-free)

// ---------------------------------------------------------------------------
// Tiled transpose: W[H,V] row-major -> g_Wt[V,H] row-major.
// ---------------------------------------------------------------------------
__global__ void __launch_bounds__(256) transpose_W_kernel(const float* __restrict__ W) {
    __shared__ float tile[32][33];
    int v0 = blockIdx.x * 32;
    int h0 = blockIdx.y * 32;
    int x = threadIdx.x;          // 0..31
    int y = threadIdx.y;          // 0..7

    #pragma unroll
    for (int i = 0; i < 32; i += 8) {
        int v = v0 + x;
        int h = h0 + y + i;
        if (v < V_N) tile[y + i][x] = W[(size_t)h * V_N + v];
    }
    __syncthreads();
    #pragma unroll
    for (int i = 0; i < 32; i += 8) {
        int v = v0 + y + i;
        int h = h0 + x;
        if (v < V_N) g_Wt[(size_t)v * H_N + h] = tile[x][y + i];
    }
}

// ---------------------------------------------------------------------------
// Gather-sum: one BLOCK (128 threads = 4 warps) per scene.
// Warp w takes 32-token chunks starting at 32*w, striding 128.
// Lane owns h = 4*lane..4*lane+3 via float4. Partial sums reduced in smem.
// ---------------------------------------------------------------------------
__global__ void __launch_bounds__(128) bow_gather_kernel(
    const int* __restrict__ tokens,
    const int* __restrict__ lengths,
    const float* __restrict__ bias,
    float* __restrict__ out)
{
    __shared__ float4 sh[3][32];

    int scene = blockIdx.x;
    int wid   = threadIdx.x >> 5;   // 0..3
    int lane  = threadIdx.x & 31;

    int len = lengths[scene];
    const int* tok = tokens + (size_t)scene * L_N;
    const float4* Wt4 = reinterpret_cast<const float4*>(g_Wt);

    float4 acc = make_float4(0.f, 0.f, 0.f, 0.f);

    // Strided 32-token chunks per warp.
    for (int base = wid * 32; base < len; base += 128) {
        int m = len - base;                 // remaining in this chunk
        if (m > 32) m = 32;
        int jj = base + lane;
        int myTok = tok[jj < L_N ? jj : (L_N - 1)];   // coalesced; extra lanes unused
        if (m == 32) {
            #pragma unroll 8
            for (int k = 0; k < 32; k++) {
                int t = __shfl_sync(0xffffffffu, myTok, k);
                float4 w = Wt4[(size_t)t * (H_N / 4) + lane];
                acc.x += w.x; acc.y += w.y; acc.z += w.z; acc.w += w.w;
            }
        } else {
            for (int k = 0; k < m; k++) {
                int t = __shfl_sync(0xffffffffu, myTok, k);
                float4 w = Wt4[(size_t)t * (H_N / 4) + lane];
                acc.x += w.x; acc.y += w.y; acc.z += w.z; acc.w += w.w;
            }
        }
    }

    // Reduce 4 warps -> warp 0, add bias, store.
    if (wid != 0) sh[wid - 1][lane] = acc;
    __syncthreads();
    if (wid == 0) {
        float4 b4 = reinterpret_cast<const float4*>(bias)[lane];
        #pragma unroll
        for (int w = 0; w < 3; w++) {
            float4 p = sh[w][lane];
            acc.x += p.x; acc.y += p.y; acc.z += p.z; acc.w += p.w;
        }
        acc.x += b4.x; acc.y += b4.y; acc.z += b4.z; acc.w += b4.w;
        reinterpret_cast<float4*>(out + (size_t)scene * H_N)[lane] = acc;
    }
}

// ---------------------------------------------------------------------------
// kernel_launch: transpose then gather (default stream, graph-capturable).
// Inputs: tokens[int32, B*L], lengths[int32, B], W[f32, H*V], b[f32, H].
// Output: f32 [B, H].
// ---------------------------------------------------------------------------
extern "C" void kernel_launch(void* const* d_in, const int* in_sizes, int n_in,
                              void* d_out, int out_size) {
    const int*   tokens  = (const int*)d_in[0];
    const int*   lengths = (const int*)d_in[1];
    const float* W       = (const float*)d_in[2];
    const float* bias    = (const float*)d_in[3];
    float*       out     = (float*)d_out;

    (void)in_sizes; (void)n_in; (void)out_size;

    dim3 tgrid((V_N + 31) / 32, H_N / 32);
    dim3 tblock(32, 8);
    transpose_W_kernel<<<tgrid, tblock>>>(W);

    bow_gather_kernel<<<B_N, 128>>>(tokens, lengths, bias, out);
}

// round 4
// speedup vs baseline: 1.2225x; 1.0627x over previous
#include <cuda_runtime.h>
#include <cuda_bf16.h>

// B=4096 scenes, L=200 padded, V=50000, H=128.
// out[i,h] = b[h] + sum_{j<len_i} W[h, tokens[i,j]]
// Wt[V,H] transpose (512B rows, L2-resident) + per-scene gather-sum.
// R3: fix MLP (reg-capped at 32 in R2) -> 64-reg budget + explicit
// 8-deep load batches. 32-bit byte offsets.

#define B_N 4096
#define L_N 200
#define V_N 50000
#define H_N 128

__device__ float g_Wt[(size_t)V_N * H_N];   // 25.6 MB scratch

// ---------------------------------------------------------------------------
// Tiled transpose: W[H,V] -> g_Wt[V,H].
// ---------------------------------------------------------------------------
__global__ void __launch_bounds__(256) transpose_W_kernel(const float* __restrict__ W) {
    __shared__ float tile[32][33];
    int v0 = blockIdx.x * 32;
    int h0 = blockIdx.y * 32;
    int x = threadIdx.x;
    int y = threadIdx.y;

    #pragma unroll
    for (int i = 0; i < 32; i += 8) {
        int v = v0 + x;
        int h = h0 + y + i;
        if (v < V_N) tile[y + i][x] = W[(size_t)h * V_N + v];
    }
    __syncthreads();
    #pragma unroll
    for (int i = 0; i < 32; i += 8) {
        int v = v0 + y + i;
        int h = h0 + x;
        if (v < V_N) g_Wt[(size_t)v * H_N + h] = tile[x][y + i];
    }
}

// ---------------------------------------------------------------------------
// Gather-sum: one block (4 warps) per scene; warp w handles chunks
// [32w, 32w+32) striding 128. Lane owns h = 4*lane..4*lane+3 (float4).
// Inner loop: batch 8 loads -> then accumulate (keeps MLP=8 in flight).
// ---------------------------------------------------------------------------
__global__ void __launch_bounds__(128, 8) bow_gather_kernel(
    const int* __restrict__ tokens,
    const int* __restrict__ lengths,
    const float* __restrict__ bias,
    float* __restrict__ out)
{
    __shared__ float4 sh[3][32];

    int scene = blockIdx.x;
    int wid   = threadIdx.x >> 5;
    int lane  = threadIdx.x & 31;

    int len = lengths[scene];
    const int* tok = tokens + (size_t)scene * L_N;
    const char* WtB = reinterpret_cast<const char*>(g_Wt);
    unsigned laneOff = (unsigned)lane * 16u;   // byte offset of this lane's float4

    float4 acc = make_float4(0.f, 0.f, 0.f, 0.f);

    for (int base = wid * 32; base < len; base += 128) {
        int m = len - base;
        if (m > 32) m = 32;
        int jj = base + lane;
        int myTok = tok[jj < L_N ? jj : (L_N - 1)];

        if (m == 32) {
            #pragma unroll
            for (int kk = 0; kk < 32; kk += 8) {
                float4 w[8];
                #pragma unroll
                for (int k = 0; k < 8; k++) {
                    int t = __shfl_sync(0xffffffffu, myTok, kk + k);
                    unsigned off = (unsigned)t * 512u + laneOff;   // t*H*4 bytes
                    w[k] = *reinterpret_cast<const float4*>(WtB + off);
                }
                #pragma unroll
                for (int k = 0; k < 8; k++) {
                    acc.x += w[k].x; acc.y += w[k].y;
                    acc.z += w[k].z; acc.w += w[k].w;
                }
            }
        } else {
            for (int k = 0; k < m; k++) {
                int t = __shfl_sync(0xffffffffu, myTok, k);
                unsigned off = (unsigned)t * 512u + laneOff;
                float4 w = *reinterpret_cast<const float4*>(WtB + off);
                acc.x += w.x; acc.y += w.y; acc.z += w.z; acc.w += w.w;
            }
        }
    }

    if (wid != 0) sh[wid - 1][lane] = acc;
    __syncthreads();
    if (wid == 0) {
        float4 b4 = reinterpret_cast<const float4*>(bias)[lane];
        #pragma unroll
        for (int w = 0; w < 3; w++) {
            float4 p = sh[w][lane];
            acc.x += p.x; acc.y += p.y; acc.z += p.z; acc.w += p.w;
        }
        acc.x += b4.x; acc.y += b4.y; acc.z += b4.z; acc.w += b4.w;
        reinterpret_cast<float4*>(out + (size_t)scene * H_N)[lane] = acc;
    }
}

// ---------------------------------------------------------------------------
extern "C" void kernel_launch(void* const* d_in, const int* in_sizes, int n_in,
                              void* d_out, int out_size) {
    const int*   tokens  = (const int*)d_in[0];
    const int*   lengths = (const int*)d_in[1];
    const float* W       = (const float*)d_in[2];
    const float* bias    = (const float*)d_in[3];
    float*       out     = (float*)d_out;

    (void)in_sizes; (void)n_in; (void)out_size;

    dim3 tgrid((V_N + 31) / 32, H_N / 32);
    dim3 tblock(32, 8);
    transpose_W_kernel<<<tgrid, tblock>>>(W);

    bow_gather_kernel<<<B_N, 128>>>(tokens, lengths, bias, out);
}

// round 5
// speedup vs baseline: 1.4632x; 1.1969x over previous
#include <cuda_runtime.h>
#include <cuda_fp16.h>
#include <cuda_bf16.h>

// B=4096 scenes, L=200 padded, V=50000, H=128.
// out[i,h] = b[h] + sum_{j<len_i} W[h, tokens[i,j]]
// R4: gather kernel was AT the practical LTS ceiling (~6300 B/cyc) with fp32
// Wt (210MB of L2 reads). Store Wt in fp16 (halve bytes), accumulate fp32.
// Expected rel_err ~3e-4 (fp16 rms rounding of summands), under 1e-3.

#define B_N 4096
#define L_N 200
#define V_N 50000
#define H_N 128

__device__ __half g_Wt[(size_t)V_N * H_N];   // 12.8 MB scratch, [V,H] row-major

// ---------------------------------------------------------------------------
// Tiled transpose+convert: W[H,V] fp32 -> g_Wt[V,H] fp16.
// ---------------------------------------------------------------------------
__global__ void __launch_bounds__(256) transpose_W_kernel(const float* __restrict__ W) {
    __shared__ float tile[32][33];
    int v0 = blockIdx.x * 32;
    int h0 = blockIdx.y * 32;
    int x = threadIdx.x;          // 0..31
    int y = threadIdx.y;          // 0..7

    #pragma unroll
    for (int i = 0; i < 32; i += 8) {
        int v = v0 + x;
        int h = h0 + y + i;
        if (v < V_N) tile[y + i][x] = W[(size_t)h * V_N + v];
    }
    __syncthreads();
    #pragma unroll
    for (int i = 0; i < 32; i += 8) {
        int v = v0 + y + i;
        int h = h0 + x;
        if (v < V_N) g_Wt[(size_t)v * H_N + h] = __float2half_rn(tile[x][y + i]);
    }
}

// ---------------------------------------------------------------------------
// Gather-sum: one block (4 warps) per scene; warp w handles 32-token chunks
// starting at 32*w, striding 128. Lane owns h = 4*lane..4*lane+3.
// Per token-row: LDG.64 (uint2 = 4 halves) per lane; convert + fp32 accum.
// Batched 8 loads deep to keep MLP high.
// ---------------------------------------------------------------------------
__global__ void __launch_bounds__(128, 10) bow_gather_kernel(
    const int* __restrict__ tokens,
    const int* __restrict__ lengths,
    const float* __restrict__ bias,
    float* __restrict__ out)
{
    __shared__ float4 sh[3][32];

    int scene = blockIdx.x;
    int wid   = threadIdx.x >> 5;
    int lane  = threadIdx.x & 31;

    int len = lengths[scene];
    const int* tok = tokens + (size_t)scene * L_N;
    const char* WtB = reinterpret_cast<const char*>(g_Wt);
    unsigned laneOff = (unsigned)lane * 8u;   // byte offset of lane's 4 halves

    float4 acc = make_float4(0.f, 0.f, 0.f, 0.f);

    for (int base = wid * 32; base < len; base += 128) {
        int m = len - base;
        if (m > 32) m = 32;
        int jj = base + lane;
        int myTok = tok[jj < L_N ? jj : (L_N - 1)];

        if (m == 32) {
            #pragma unroll
            for (int kk = 0; kk < 32; kk += 8) {
                uint2 w[8];
                #pragma unroll
                for (int k = 0; k < 8; k++) {
                    int t = __shfl_sync(0xffffffffu, myTok, kk + k);
                    unsigned off = (unsigned)t * 256u + laneOff;   // t*H*2 bytes
                    w[k] = *reinterpret_cast<const uint2*>(WtB + off);
                }
                #pragma unroll
                for (int k = 0; k < 8; k++) {
                    float2 f01 = __half22float2(*reinterpret_cast<__half2*>(&w[k].x));
                    float2 f23 = __half22float2(*reinterpret_cast<__half2*>(&w[k].y));
                    acc.x += f01.x; acc.y += f01.y;
                    acc.z += f23.x; acc.w += f23.y;
                }
            }
        } else {
            for (int k = 0; k < m; k++) {
                int t = __shfl_sync(0xffffffffu, myTok, k);
                unsigned off = (unsigned)t * 256u + laneOff;
                uint2 w = *reinterpret_cast<const uint2*>(WtB + off);
                float2 f01 = __half22float2(*reinterpret_cast<__half2*>(&w.x));
                float2 f23 = __half22float2(*reinterpret_cast<__half2*>(&w.y));
                acc.x += f01.x; acc.y += f01.y;
                acc.z += f23.x; acc.w += f23.y;
            }
        }
    }

    if (wid != 0) sh[wid - 1][lane] = acc;
    __syncthreads();
    if (wid == 0) {
        float4 b4 = reinterpret_cast<const float4*>(bias)[lane];
        #pragma unroll
        for (int w = 0; w < 3; w++) {
            float4 p = sh[w][lane];
            acc.x += p.x; acc.y += p.y; acc.z += p.z; acc.w += p.w;
        }
        acc.x += b4.x; acc.y += b4.y; acc.z += b4.z; acc.w += b4.w;
        reinterpret_cast<float4*>(out + (size_t)scene * H_N)[lane] = acc;
    }
}

// ---------------------------------------------------------------------------
extern "C" void kernel_launch(void* const* d_in, const int* in_sizes, int n_in,
                              void* d_out, int out_size) {
    const int*   tokens  = (const int*)d_in[0];
    const int*   lengths = (const int*)d_in[1];
    const float* W       = (const float*)d_in[2];
    const float* bias    = (const float*)d_in[3];
    float*       out     = (float*)d_out;

    (void)in_sizes; (void)n_in; (void)out_size;

    dim3 tgrid((V_N + 31) / 32, H_N / 32);
    dim3 tblock(32, 8);
    transpose_W_kernel<<<tgrid, tblock>>>(W);

    bow_gather_kernel<<<B_N, 128>>>(tokens, lengths, bias, out);
}

// round 6
// speedup vs baseline: 1.5652x; 1.0697x over previous
#include <cuda_runtime.h>
#include <cuda_fp16.h>
#include <cuda_bf16.h>

// B=4096 scenes, L=200 padded, V=50000, H=128.
// out[i,h] = b[h] + sum_{j<len_i} W[h, tokens[i,j]]
// Wt[V,H] fp16 (L2-resident) + per-scene gather.
// R5: gather is issue/latency-bound (L2 25%, issue 43%). Pair adjacent tokens
// with HADD2 in fp16 before converting: ~40% fewer instrs/token, F2F halved.
// Error budget: pairing adds ~3e-4 rel (one fp16 add of two stored values),
// total ~4e-4 < 1e-3. fp32 accumulation of pair-sums.

#define B_N 4096
#define L_N 200
#define V_N 50000
#define H_N 128

__device__ __half g_Wt[(size_t)V_N * H_N];   // 12.8 MB scratch, [V,H] row-major

// ---------------------------------------------------------------------------
// Tiled transpose+convert: W[H,V] fp32 -> g_Wt[V,H] fp16. half2 stores.
// ---------------------------------------------------------------------------
__global__ void __launch_bounds__(256) transpose_W_kernel(const float* __restrict__ W) {
    __shared__ float tile[32][33];
    int v0 = blockIdx.x * 32;
    int h0 = blockIdx.y * 32;
    int x = threadIdx.x;          // 0..31
    int y = threadIdx.y;          // 0..7

    #pragma unroll
    for (int i = 0; i < 32; i += 8) {
        int v = v0 + x;
        int h = h0 + y + i;
        if (v < V_N) tile[y + i][x] = W[(size_t)h * V_N + v];
    }
    __syncthreads();

    // Write phase: each thread writes one half2 (two h) per iter; 2 iters
    // cover 32 v-rows. Coalesced 4-byte stores along h.
    int tid = threadIdx.y * 32 + threadIdx.x;   // 0..255
    int hp  = tid & 15;                         // h-pair index 0..15
    #pragma unroll
    for (int iter = 0; iter < 2; iter++) {
        int vloc = iter * 16 + (tid >> 4);      // 0..31
        int v = v0 + vloc;
        if (v < V_N) {
            __half2 val = __floats2half2_rn(tile[2 * hp][vloc], tile[2 * hp + 1][vloc]);
            *reinterpret_cast<__half2*>(&g_Wt[(size_t)v * H_N + h0 + 2 * hp]) = val;
        }
    }
}

// ---------------------------------------------------------------------------
// Gather-sum: one block (4 warps) per scene; warp w owns 32-token chunks at
// 32w, striding 128. Lane owns h = 4*lane..4*lane+3 (uint2 = 4 halves).
// Tokens processed in PAIRS: w(t0)+w(t1) via HADD2, then convert + fp32 acc.
// Batches of 4 pairs (8 LDGs in flight).
// ---------------------------------------------------------------------------
__global__ void __launch_bounds__(128, 12) bow_gather_kernel(
    const int* __restrict__ tokens,
    const int* __restrict__ lengths,
    const float* __restrict__ bias,
    float* __restrict__ out)
{
    __shared__ float4 sh[3][32];

    int scene = blockIdx.x;
    int wid   = threadIdx.x >> 5;
    int lane  = threadIdx.x & 31;

    int len = lengths[scene];
    const int* tok = tokens + (size_t)scene * L_N;
    const char* WtB = reinterpret_cast<const char*>(g_Wt);
    unsigned laneOff = (unsigned)lane * 8u;   // byte offset of lane's 4 halves

    float4 acc = make_float4(0.f, 0.f, 0.f, 0.f);

    for (int base = wid * 32; base < len; base += 128) {
        int m = len - base;
        if (m > 32) m = 32;
        int jj = base + lane;
        int myTok = tok[jj < L_N ? jj : (L_N - 1)];

        if (m == 32) {
            #pragma unroll
            for (int qq = 0; qq < 16; qq += 4) {
                uint2 wa[4], wb[4];
                #pragma unroll
                for (int k = 0; k < 4; k++) {
                    int t0 = __shfl_sync(0xffffffffu, myTok, 2 * (qq + k));
                    int t1 = __shfl_sync(0xffffffffu, myTok, 2 * (qq + k) + 1);
                    wa[k] = *reinterpret_cast<const uint2*>(WtB + (unsigned)t0 * 256u + laneOff);
                    wb[k] = *reinterpret_cast<const uint2*>(WtB + (unsigned)t1 * 256u + laneOff);
                }
                #pragma unroll
                for (int k = 0; k < 4; k++) {
                    __half2 s0 = __hadd2(*reinterpret_cast<__half2*>(&wa[k].x),
                                         *reinterpret_cast<__half2*>(&wb[k].x));
                    __half2 s1 = __hadd2(*reinterpret_cast<__half2*>(&wa[k].y),
                                         *reinterpret_cast<__half2*>(&wb[k].y));
                    float2 f01 = __half22float2(s0);
                    float2 f23 = __half22float2(s1);
                    acc.x += f01.x; acc.y += f01.y;
                    acc.z += f23.x; acc.w += f23.y;
                }
            }
        } else {
            int npair = m >> 1;
            for (int q = 0; q < npair; q++) {
                int t0 = __shfl_sync(0xffffffffu, myTok, 2 * q);
                int t1 = __shfl_sync(0xffffffffu, myTok, 2 * q + 1);
                uint2 wa = *reinterpret_cast<const uint2*>(WtB + (unsigned)t0 * 256u + laneOff);
                uint2 wb = *reinterpret_cast<const uint2*>(WtB + (unsigned)t1 * 256u + laneOff);
                __half2 s0 = __hadd2(*reinterpret_cast<__half2*>(&wa.x),
                                     *reinterpret_cast<__half2*>(&wb.x));
                __half2 s1 = __hadd2(*reinterpret_cast<__half2*>(&wa.y),
                                     *reinterpret_cast<__half2*>(&wb.y));
                float2 f01 = __half22float2(s0);
                float2 f23 = __half22float2(s1);
                acc.x += f01.x; acc.y += f01.y;
                acc.z += f23.x; acc.w += f23.y;
            }
            if (m & 1) {
                int t = __shfl_sync(0xffffffffu, myTok, m - 1);
                uint2 w = *reinterpret_cast<const uint2*>(WtB + (unsigned)t * 256u + laneOff);
                float2 f01 = __half22float2(*reinterpret_cast<__half2*>(&w.x));
                float2 f23 = __half22float2(*reinterpret_cast<__half2*>(&w.y));
                acc.x += f01.x; acc.y += f01.y;
                acc.z += f23.x; acc.w += f23.y;
            }
        }
    }

    if (wid != 0) sh[wid - 1][lane] = acc;
    __syncthreads();
    if (wid == 0) {
        float4 b4 = reinterpret_cast<const float4*>(bias)[lane];
        #pragma unroll
        for (int w = 0; w < 3; w++) {
            float4 p = sh[w][lane];
            acc.x += p.x; acc.y += p.y; acc.z += p.z; acc.w += p.w;
        }
        acc.x += b4.x; acc.y += b4.y; acc.z += b4.z; acc.w += b4.w;
        reinterpret_cast<float4*>(out + (size_t)scene * H_N)[lane] = acc;
    }
}

// ---------------------------------------------------------------------------
extern "C" void kernel_launch(void* const* d_in, const int* in_sizes, int n_in,
                              void* d_out, int out_size) {
    const int*   tokens  = (const int*)d_in[0];
    const int*   lengths = (const int*)d_in[1];
    const float* W       = (const float*)d_in[2];
    const float* bias    = (const float*)d_in[3];
    float*       out     = (float*)d_out;

    (void)in_sizes; (void)n_in; (void)out_size;

    dim3 tgrid((V_N + 31) / 32, H_N / 32);
    dim3 tblock(32, 8);
    transpose_W_kernel<<<tgrid, tblock>>>(W);

    bow_gather_kernel<<<B_N, 128>>>(tokens, lengths, bias, out);
}